// round 12
// baseline (speedup 1.0000x reference)
#include <cuda_runtime.h>
#include <cuda_fp16.h>
#include <cstdint>

#define N_NODES 50000
#define N_EDGES 800000

// ---------------- scratch (no allocations allowed) ----------------
__device__ __align__(16) __half g_GA[N_NODES * 512];   // G0, then G2
__device__ __align__(16) __half g_GB[N_NODES * 512];   // G1
__device__ __align__(16) __half g_w16[327680];         // stacked [Ws;Wn] per layer
__device__ int g_deg[N_NODES];
__device__ int g_row[N_NODES + 1];
__device__ int g_cur[N_NODES];
__device__ int g_csr[N_EDGES];

// ---------------- fp32 -> fp16 weight convert (stacked) ----------------
__global__ void k_cvt_w(const float* __restrict__ w0, const float* __restrict__ w1,
                        const float* __restrict__ w2, const float* __restrict__ w3,
                        const float* __restrict__ w4, const float* __restrict__ w5) {
    int i = (blockIdx.x * blockDim.x + threadIdx.x) * 4;
    if (i >= 327680) return;
    const float* src;
    int off;
    if (i < 262144) {
        int seg = i >> 16;
        src = (seg == 0) ? w0 : (seg == 1) ? w1 : (seg == 2) ? w2 : w3;
        off = i & 65535;
    } else {
        src = (i < 294912) ? w4 : w5;
        off = (i - 262144) & 32767;
    }
    float4 v = *(const float4*)(src + off);
    __half2 a = __floats2half2_rn(v.x, v.y);
    __half2 b = __floats2half2_rn(v.z, v.w);
    uint2 o;
    o.x = *(uint32_t*)&a;
    o.y = *(uint32_t*)&b;
    *(uint2*)(g_w16 + i) = o;
}

// ---------------- CSR build ----------------
__global__ void k_count4(const int4* __restrict__ dst4, int e4) {
    int i = blockIdx.x * blockDim.x + threadIdx.x;
    if (i < e4) {
        int4 d = __ldg(&dst4[i]);
        atomicAdd(&g_deg[d.x], 1);
        atomicAdd(&g_deg[d.y], 1);
        atomicAdd(&g_deg[d.z], 1);
        atomicAdd(&g_deg[d.w], 1);
    }
}

__global__ void k_scan(int n) {
    __shared__ int wsum[32];
    __shared__ int carry;
    int lane = threadIdx.x & 31, wid = threadIdx.x >> 5;
    if (threadIdx.x == 0) { carry = 0; g_row[0] = 0; }
    __syncthreads();
    for (int base = 0; base < n; base += 1024) {
        int i = base + threadIdx.x;
        int v = (i < n) ? g_deg[i] : 0;
        int x = v;
#pragma unroll
        for (int o = 1; o < 32; o <<= 1) {
            int t = __shfl_up_sync(0xffffffffu, x, o);
            if (lane >= o) x += t;
        }
        if (lane == 31) wsum[wid] = x;
        __syncthreads();
        if (wid == 0) {
            int w = wsum[lane];
#pragma unroll
            for (int o = 1; o < 32; o <<= 1) {
                int t = __shfl_up_sync(0xffffffffu, w, o);
                if (lane >= o) w += t;
            }
            wsum[lane] = w;
        }
        __syncthreads();
        int incl = x + (wid ? wsum[wid - 1] : 0) + carry;
        if (i < n) {
            g_row[i + 1] = incl;
            g_cur[i] = incl - v;
        }
        __syncthreads();
        if (threadIdx.x == 1023) carry = incl;
        __syncthreads();
    }
}

__global__ void k_fill4(const int4* __restrict__ src4, const int4* __restrict__ dst4,
                        int e4) {
    int i = blockIdx.x * blockDim.x + threadIdx.x;
    if (i < e4) {
        int4 s = __ldg(&src4[i]);
        int4 d = __ldg(&dst4[i]);
        g_csr[atomicAdd(&g_cur[d.x], 1)] = s.x;
        g_csr[atomicAdd(&g_cur[d.y], 1)] = s.y;
        g_csr[atomicAdd(&g_cur[d.z], 1)] = s.z;
        g_csr[atomicAdd(&g_cur[d.w], 1)] = s.w;
    }
}

// ---------------- final agg + combine (fp32 out, no relu) ----------------
// G rows [hs|hn] width 256 (F=128). out[v] = hs[v] + mean_u(hn[u]) + b.
__global__ void k_aggc_f(const __half* __restrict__ G, const float* __restrict__ bias,
                         float* __restrict__ out, int n) {
    int v = (blockIdx.x * blockDim.x + threadIdx.x) >> 5;
    if (v >= n) return;
    int lane = threadIdx.x & 31;
    int s = g_row[v], e = g_row[v + 1];
    float a0 = 0.f, a1 = 0.f, a2 = 0.f, a3 = 0.f;
    int i = s;
    for (; i + 2 <= e; i += 2) {
        const __half* p0 = G + (size_t)g_csr[i]     * 256 + 128;
        const __half* p1 = G + (size_t)g_csr[i + 1] * 256 + 128;
        uint2 t0 = __ldg((const uint2*)p0 + lane);
        uint2 t1 = __ldg((const uint2*)p1 + lane);
        float2 q;
        q = __half22float2(*(__half2*)&t0.x); a0 += q.x; a1 += q.y;
        q = __half22float2(*(__half2*)&t0.y); a2 += q.x; a3 += q.y;
        q = __half22float2(*(__half2*)&t1.x); a0 += q.x; a1 += q.y;
        q = __half22float2(*(__half2*)&t1.y); a2 += q.x; a3 += q.y;
    }
    if (i < e) {
        const __half* p0 = G + (size_t)g_csr[i] * 256 + 128;
        uint2 t0 = __ldg((const uint2*)p0 + lane);
        float2 q;
        q = __half22float2(*(__half2*)&t0.x); a0 += q.x; a1 += q.y;
        q = __half22float2(*(__half2*)&t0.y); a2 += q.x; a3 += q.y;
    }
    float inv = 1.0f / (float)max(e - s, 1);
    uint2 hv = __ldg((const uint2*)(G + (size_t)v * 256) + lane);
    float2 q0 = __half22float2(*(__half2*)&hv.x);
    float2 q1 = __half22float2(*(__half2*)&hv.y);
    float4 r;
    r.x = q0.x + a0 * inv + __ldg(&bias[lane * 4 + 0]);
    r.y = q0.y + a1 * inv + __ldg(&bias[lane * 4 + 1]);
    r.z = q1.x + a2 * inv + __ldg(&bias[lane * 4 + 2]);
    r.w = q1.y + a3 * inv + __ldg(&bias[lane * 4 + 3]);
    *(float4*)(out + (size_t)v * 128 + lane * 4) = r;
}

// ---------------- fused gather + GEMM ----------------
// If GATHER: A row v = relu(hs(Gin[v]) + mean_u(hn(Gin[u])) + bias)  (Gin rows 512)
// else:      A row v = fp16(x[v])                                     (x fp32, 256)
// Then Gout[tile] = A @ W^T   (W [NOUT,256] fp16, raw fp16 out, no bias).
// 512 threads = 16 warps. A smem 128x264; B double-buffered 128x264 per stage.

#define PADA 264
#define A_BYTES (128 * PADA * 2)        // 67584
#define SMEM_FUSED (3 * A_BYTES)        // 202752

__device__ __forceinline__ void ldm_x4(uint32_t& r0, uint32_t& r1, uint32_t& r2,
                                       uint32_t& r3, uint32_t addr) {
    asm volatile("ldmatrix.sync.aligned.m8n8.x4.shared.b16 {%0,%1,%2,%3}, [%4];"
                 : "=r"(r0), "=r"(r1), "=r"(r2), "=r"(r3) : "r"(addr));
}

__device__ __forceinline__ void mma16816(float* c, const uint32_t* a, const uint32_t* b) {
    asm volatile(
        "mma.sync.aligned.m16n8k16.row.col.f32.f16.f16.f32 "
        "{%0,%1,%2,%3}, {%4,%5,%6,%7}, {%8,%9}, {%0,%1,%2,%3};"
        : "+f"(c[0]), "+f"(c[1]), "+f"(c[2]), "+f"(c[3])
        : "r"(a[0]), "r"(a[1]), "r"(a[2]), "r"(a[3]), "r"(b[0]), "r"(b[1]));
}

__device__ __forceinline__ void cpa16(uint32_t sdst, const void* gsrc) {
    asm volatile("cp.async.ca.shared.global [%0], [%1], 16;"
                 :: "r"(sdst), "l"(gsrc));
}

template <int NOUT, int GATHER>
__global__ __launch_bounds__(512) void k_fused(
    const void* __restrict__ Xin, const __half* __restrict__ W,
    const float* __restrict__ bias, __half* __restrict__ Gout, int M)
{
    extern __shared__ __align__(16) __half smem[];
    __half* Asm = smem;                       // 128 x PADA
    const int tid = threadIdx.x;
    const int lane = tid & 31, warp = tid >> 5;
    const int bm = blockIdx.x * 128;
    constexpr int NB = NOUT / 128;

    uint32_t sbase = (uint32_t)__cvta_generic_to_shared(smem);
    uint32_t bA = sbase;
    uint32_t sB[2] = { sbase + A_BYTES, sbase + 2 * A_BYTES };

    // ---- issue B(0) prefetch (overlaps the A phase) ----
#define ISSUE_B(nb, buf) do {                                                  \
    _Pragma("unroll")                                                          \
    for (int p_ = 0; p_ < 8; p_++) {                                           \
        int idx_ = tid + p_ * 512;                                             \
        int row_ = idx_ >> 5, ch_ = idx_ & 31;                                 \
        cpa16(sB[buf] + (row_ * PADA + ch_ * 8) * 2,                           \
              W + (size_t)((nb) * 128 + row_) * 256 + ch_ * 8);                \
    }                                                                          \
    asm volatile("cp.async.commit_group;");                                    \
} while (0)

    ISSUE_B(0, 0);

    // ---- A phase: 16 warps x 8 rows ----
    for (int t = 0; t < 8; t++) {
        int row = warp * 8 + t;
        int v = bm + row;
        float r[8];
#pragma unroll
        for (int k = 0; k < 8; k++) r[k] = 0.f;

        if (v < M) {
            if (GATHER) {
                const __half* Gin = (const __half*)Xin;
                int s = g_row[v], e = g_row[v + 1];
                float a[8];
#pragma unroll
                for (int k = 0; k < 8; k++) a[k] = 0.f;
                int i = s;
                for (; i + 4 <= e; i += 4) {
                    int u0 = g_csr[i], u1 = g_csr[i + 1];
                    int u2 = g_csr[i + 2], u3 = g_csr[i + 3];
                    uint4 t0 = __ldg((const uint4*)(Gin + (size_t)u0 * 512 + 256) + lane);
                    uint4 t1 = __ldg((const uint4*)(Gin + (size_t)u1 * 512 + 256) + lane);
                    uint4 t2 = __ldg((const uint4*)(Gin + (size_t)u2 * 512 + 256) + lane);
                    uint4 t3 = __ldg((const uint4*)(Gin + (size_t)u3 * 512 + 256) + lane);
                    float2 q;
#define ACC4(T) \
    q = __half22float2(*(__half2*)&T.x); a[0] += q.x; a[1] += q.y;             \
    q = __half22float2(*(__half2*)&T.y); a[2] += q.x; a[3] += q.y;             \
    q = __half22float2(*(__half2*)&T.z); a[4] += q.x; a[5] += q.y;             \
    q = __half22float2(*(__half2*)&T.w); a[6] += q.x; a[7] += q.y;
                    ACC4(t0) ACC4(t1) ACC4(t2) ACC4(t3)
                }
                for (; i < e; i++) {
                    uint4 t0 = __ldg((const uint4*)(Gin + (size_t)g_csr[i] * 512 + 256) + lane);
                    float2 q;
                    ACC4(t0)
#undef ACC4
                }
                float inv = 1.0f / (float)max(e - s, 1);
                uint4 hv = __ldg((const uint4*)(Gin + (size_t)v * 512) + lane);
                float2 q;
                q = __half22float2(*(__half2*)&hv.x); r[0] = q.x; r[1] = q.y;
                q = __half22float2(*(__half2*)&hv.y); r[2] = q.x; r[3] = q.y;
                q = __half22float2(*(__half2*)&hv.z); r[4] = q.x; r[5] = q.y;
                q = __half22float2(*(__half2*)&hv.w); r[6] = q.x; r[7] = q.y;
#pragma unroll
                for (int k = 0; k < 8; k++) {
                    r[k] += a[k] * inv + __ldg(&bias[lane * 8 + k]);
                    r[k] = fmaxf(r[k], 0.f);
                }
            } else {
                const float* x = (const float*)Xin;
                float4 f0 = __ldg((const float4*)(x + (size_t)v * 256) + lane * 2);
                float4 f1 = __ldg((const float4*)(x + (size_t)v * 256) + lane * 2 + 1);
                r[0] = f0.x; r[1] = f0.y; r[2] = f0.z; r[3] = f0.w;
                r[4] = f1.x; r[5] = f1.y; r[6] = f1.z; r[7] = f1.w;
            }
        }
        __half2 h0 = __floats2half2_rn(r[0], r[1]);
        __half2 h1 = __floats2half2_rn(r[2], r[3]);
        __half2 h2 = __floats2half2_rn(r[4], r[5]);
        __half2 h3 = __floats2half2_rn(r[6], r[7]);
        uint4 pk;
        pk.x = *(uint32_t*)&h0; pk.y = *(uint32_t*)&h1;
        pk.z = *(uint32_t*)&h2; pk.w = *(uint32_t*)&h3;
        *(uint4*)&Asm[row * PADA + lane * 8] = pk;
    }

    // ---- GEMM: 16 warps, warp tile 32(M) x 32(N), loop over N-blocks ----
    const int wm = warp >> 2, wn = warp & 3;
    const int g = lane >> 2, cq = lane & 3;
    const int j = lane & 7, t = lane >> 3;

    for (int nb = 0; nb < NB; nb++) {
        if (nb + 1 < NB) {
            ISSUE_B(nb + 1, (nb + 1) & 1);
            asm volatile("cp.async.wait_group 1;");
        } else {
            asm volatile("cp.async.wait_group 0;");
        }
        __syncthreads();   // B(nb) visible; also orders A writes (first iter)

        uint32_t bB = sB[nb & 1];
        float acc[2][4][4];
#pragma unroll
        for (int mi = 0; mi < 2; mi++)
#pragma unroll
            for (int ni = 0; ni < 4; ni++)
#pragma unroll
                for (int rr = 0; rr < 4; rr++) acc[mi][ni][rr] = 0.f;

#pragma unroll
        for (int k16 = 0; k16 < 16; k16++) {
            int kh0 = k16 * 16;
            uint32_t a[2][4];
#pragma unroll
            for (int mi = 0; mi < 2; mi++) {
                int rowa = wm * 32 + mi * 16 + j + (t & 1) * 8;
                int cola = kh0 + (t >> 1) * 8;
                ldm_x4(a[mi][0], a[mi][1], a[mi][2], a[mi][3],
                       bA + (rowa * PADA + cola) * 2);
            }
            uint32_t b[4][2];
#pragma unroll
            for (int q = 0; q < 2; q++) {
                int rowb = wn * 32 + q * 16 + j + (t >> 1) * 8;
                int colb = kh0 + (t & 1) * 8;
                uint32_t r0, r1, r2, r3;
                ldm_x4(r0, r1, r2, r3, bB + (rowb * PADA + colb) * 2);
                b[2 * q][0] = r0; b[2 * q][1] = r1;
                b[2 * q + 1][0] = r2; b[2 * q + 1][1] = r3;
            }
#pragma unroll
            for (int mi = 0; mi < 2; mi++)
#pragma unroll
                for (int ni = 0; ni < 4; ni++)
                    mma16816(acc[mi][ni], a[mi], b[ni]);
        }

        // epilogue (raw fp16)
#pragma unroll
        for (int mi = 0; mi < 2; mi++) {
            int r0 = bm + wm * 32 + mi * 16 + g;
            int r1 = r0 + 8;
#pragma unroll
            for (int ni = 0; ni < 4; ni++) {
                int col = nb * 128 + wn * 32 + ni * 8 + 2 * cq;
                if (r0 < M)
                    *(__half2*)&Gout[(size_t)r0 * NOUT + col] =
                        __floats2half2_rn(acc[mi][ni][0], acc[mi][ni][1]);
                if (r1 < M)
                    *(__half2*)&Gout[(size_t)r1 * NOUT + col] =
                        __floats2half2_rn(acc[mi][ni][2], acc[mi][ni][3]);
            }
        }
        if (nb + 1 < NB) __syncthreads();  // protect buf (nb&1) before overwrite
    }
#undef ISSUE_B
}

// ---------------- host ----------------
extern "C" void kernel_launch(void* const* d_in, const int* in_sizes, int n_in,
                              void* d_out, int out_size) {
    const float* x = nullptr;
    const int *src = nullptr, *dstp = nullptr;
    const float* Ws[3] = {0, 0, 0};
    const float* Wn[3] = {0, 0, 0};
    const float* bs[3] = {0, 0, 0};
    int c65536 = 0, c256 = 0, c32768 = 0, c800k = 0;
    for (int i = 0; i < n_in; i++) {
        int sz = in_sizes[i];
        void* p = d_in[i];
        if (sz == 12800000) {
            x = (const float*)p;
        } else if (sz == 800000) {
            if (c800k++ == 0) src = (const int*)p; else dstp = (const int*)p;
        } else if (sz == 65536) {
            int k = c65536++;
            if (k == 0) Ws[0] = (const float*)p;
            else if (k == 1) Wn[0] = (const float*)p;
            else if (k == 2) Ws[1] = (const float*)p;
            else Wn[1] = (const float*)p;
        } else if (sz == 32768) {
            if (c32768++ == 0) Ws[2] = (const float*)p; else Wn[2] = (const float*)p;
        } else if (sz == 256) {
            if (c256++ == 0) bs[0] = (const float*)p; else bs[1] = (const float*)p;
        } else if (sz == 128) {
            bs[2] = (const float*)p;
        }
    }

    __half *GA, *GB, *w16;
    int* degp;
    cudaGetSymbolAddress((void**)&GA,   g_GA);
    cudaGetSymbolAddress((void**)&GB,   g_GB);
    cudaGetSymbolAddress((void**)&w16,  g_w16);
    cudaGetSymbolAddress((void**)&degp, g_deg);

    static cudaStream_t s2 = nullptr;
    static cudaEvent_t ev0, evS;
    if (!s2) {
        cudaStreamCreateWithFlags(&s2, cudaStreamNonBlocking);
        cudaEventCreateWithFlags(&ev0, cudaEventDisableTiming);
        cudaEventCreateWithFlags(&evS, cudaEventDisableTiming);
        cudaFuncSetAttribute((const void*)k_fused<512, 0>,
                             cudaFuncAttributeMaxDynamicSharedMemorySize, SMEM_FUSED);
        cudaFuncSetAttribute((const void*)k_fused<512, 1>,
                             cudaFuncAttributeMaxDynamicSharedMemorySize, SMEM_FUSED);
        cudaFuncSetAttribute((const void*)k_fused<256, 1>,
                             cudaFuncAttributeMaxDynamicSharedMemorySize, SMEM_FUSED);
    }

    const int n = N_NODES, e = N_EDGES;
    int gx = (n + 127) / 128;   // 391

    // fork: s2 builds CSR while stream0 does weight cvt + layer-0 GEMM
    cudaEventRecord(ev0, 0);
    cudaStreamWaitEvent(s2, ev0, 0);

    cudaMemsetAsync(degp, 0, n * sizeof(int), s2);
    int e4 = e / 4;
    k_count4<<<(e4 + 255) / 256, 256, 0, s2>>>((const int4*)dstp, e4);
    k_scan<<<1, 1024, 0, s2>>>(n);
    k_fill4<<<(e4 + 255) / 256, 256, 0, s2>>>((const int4*)src, (const int4*)dstp, e4);
    cudaEventRecord(evS, s2);

    k_cvt_w<<<320, 256>>>(Ws[0], Wn[0], Ws[1], Wn[1], Ws[2], Wn[2]);
    // layer 0: G0 = x @ [Ws0;Wn0]^T   (x converted in-kernel; no CSR needed)
    k_fused<512, 0><<<gx, 512, SMEM_FUSED>>>(x, w16 + 0, nullptr, GA, n);

    cudaStreamWaitEvent(0, evS, 0);   // gather layers need CSR

    // layer 1: h1 = relu(aggc(G0, b0)) on the fly; G1 = h1 @ [Ws1;Wn1]^T
    k_fused<512, 1><<<gx, 512, SMEM_FUSED>>>(GA, w16 + 131072, bs[0], GB, n);
    // layer 2: h2 = relu(aggc(G1, b1)); G2 = h2 @ [Ws2;Wn2]^T  (rows 256-wide)
    k_fused<256, 1><<<gx, 512, SMEM_FUSED>>>(GB, w16 + 262144, bs[1], GA, n);
    // final: out = hs2 + mean(hn2) + b2   (fp32, no relu)
    int aggG = (n * 32 + 255) / 256;
    k_aggc_f<<<aggG, 256>>>(GA, bs[2], (float*)d_out, n);
}

// round 13
// speedup vs baseline: 1.1392x; 1.1392x over previous
#include <cuda_runtime.h>
#include <cuda_fp16.h>
#include <cstdint>

#define N_NODES 50000
#define N_EDGES 800000

// ---------------- scratch (no allocations allowed) ----------------
__device__ __align__(16) __half g_h16 [N_NODES * 256];   // layer-2 input
__device__ __align__(16) __half g_h16b[N_NODES * 256];   // layer-1 input
__device__ __align__(16) __half g_G   [N_NODES * 512];   // GEMM output [hs|hn]
__device__ __align__(16) __half g_w16[327680];           // stacked [Ws;Wn] per layer
__device__ int g_deg[N_NODES];
__device__ int g_row[N_NODES + 1];
__device__ int g_cur[N_NODES];
__device__ int g_csr[N_EDGES];

// ---------------- fp32 -> fp16 weight convert (stacked) ----------------
__global__ void k_cvt_w(const float* __restrict__ w0, const float* __restrict__ w1,
                        const float* __restrict__ w2, const float* __restrict__ w3,
                        const float* __restrict__ w4, const float* __restrict__ w5) {
    int i = (blockIdx.x * blockDim.x + threadIdx.x) * 4;
    if (i >= 327680) return;
    const float* src;
    int off;
    if (i < 262144) {
        int seg = i >> 16;
        src = (seg == 0) ? w0 : (seg == 1) ? w1 : (seg == 2) ? w2 : w3;
        off = i & 65535;
    } else {
        src = (i < 294912) ? w4 : w5;
        off = (i - 262144) & 32767;
    }
    float4 v = *(const float4*)(src + off);
    __half2 a = __floats2half2_rn(v.x, v.y);
    __half2 b = __floats2half2_rn(v.z, v.w);
    uint2 o;
    o.x = *(uint32_t*)&a;
    o.y = *(uint32_t*)&b;
    *(uint2*)(g_w16 + i) = o;
}

// ---------------- CSR build (int4-vectorized edge reads) ----------------
__global__ void k_count4(const int4* __restrict__ dst4, int e4) {
    int i = blockIdx.x * blockDim.x + threadIdx.x;
    if (i < e4) {
        int4 d = __ldg(&dst4[i]);
        atomicAdd(&g_deg[d.x], 1);
        atomicAdd(&g_deg[d.y], 1);
        atomicAdd(&g_deg[d.z], 1);
        atomicAdd(&g_deg[d.w], 1);
    }
}

__global__ void k_scan(int n) {
    __shared__ int wsum[32];
    __shared__ int carry;
    int lane = threadIdx.x & 31, wid = threadIdx.x >> 5;
    if (threadIdx.x == 0) { carry = 0; g_row[0] = 0; }
    __syncthreads();
    for (int base = 0; base < n; base += 1024) {
        int i = base + threadIdx.x;
        int v = (i < n) ? g_deg[i] : 0;
        int x = v;
#pragma unroll
        for (int o = 1; o < 32; o <<= 1) {
            int t = __shfl_up_sync(0xffffffffu, x, o);
            if (lane >= o) x += t;
        }
        if (lane == 31) wsum[wid] = x;
        __syncthreads();
        if (wid == 0) {
            int w = wsum[lane];
#pragma unroll
            for (int o = 1; o < 32; o <<= 1) {
                int t = __shfl_up_sync(0xffffffffu, w, o);
                if (lane >= o) w += t;
            }
            wsum[lane] = w;
        }
        __syncthreads();
        int incl = x + (wid ? wsum[wid - 1] : 0) + carry;
        if (i < n) {
            g_row[i + 1] = incl;
            g_cur[i] = incl - v;
        }
        __syncthreads();
        if (threadIdx.x == 1023) carry = incl;
        __syncthreads();
    }
}

__global__ void k_fill4(const int4* __restrict__ src4, const int4* __restrict__ dst4,
                        int e4) {
    int i = blockIdx.x * blockDim.x + threadIdx.x;
    if (i < e4) {
        int4 s = __ldg(&src4[i]);
        int4 d = __ldg(&dst4[i]);
        g_csr[atomicAdd(&g_cur[d.x], 1)] = s.x;
        g_csr[atomicAdd(&g_cur[d.y], 1)] = s.y;
        g_csr[atomicAdd(&g_cur[d.z], 1)] = s.z;
        g_csr[atomicAdd(&g_cur[d.w], 1)] = s.w;
    }
}

// ---------------- agg + combine ----------------
// G rows are [hs | hn], width 2F halves. out[v] = act(hs[v] + mean_u(hn[u]) + b).
// One warp per node; lane covers F/32 columns.
template <int F, int OUT_HALF, int RELU>
__global__ void k_aggc(const __half* __restrict__ G, const float* __restrict__ bias,
                       void* __restrict__ outv, int n) {
    int v = (blockIdx.x * blockDim.x + threadIdx.x) >> 5;
    if (v >= n) return;
    int lane = threadIdx.x & 31;
    constexpr int GW = 2 * F;
    constexpr int CPL = F / 32;
    int s = g_row[v], e = g_row[v + 1];

    float a[CPL];
#pragma unroll
    for (int k = 0; k < CPL; k++) a[k] = 0.f;

    int i = s;
    if constexpr (F == 256) {
        for (; i + 2 <= e; i += 2) {
            const __half* p0 = G + (size_t)g_csr[i]     * GW + F;
            const __half* p1 = G + (size_t)g_csr[i + 1] * GW + F;
            uint4 t0 = __ldg((const uint4*)p0 + lane);
            uint4 t1 = __ldg((const uint4*)p1 + lane);
            float2 q;
            q = __half22float2(*(__half2*)&t0.x); a[0] += q.x; a[1] += q.y;
            q = __half22float2(*(__half2*)&t0.y); a[2] += q.x; a[3] += q.y;
            q = __half22float2(*(__half2*)&t0.z); a[4] += q.x; a[5] += q.y;
            q = __half22float2(*(__half2*)&t0.w); a[6] += q.x; a[7] += q.y;
            q = __half22float2(*(__half2*)&t1.x); a[0] += q.x; a[1] += q.y;
            q = __half22float2(*(__half2*)&t1.y); a[2] += q.x; a[3] += q.y;
            q = __half22float2(*(__half2*)&t1.z); a[4] += q.x; a[5] += q.y;
            q = __half22float2(*(__half2*)&t1.w); a[6] += q.x; a[7] += q.y;
        }
        if (i < e) {
            const __half* p0 = G + (size_t)g_csr[i] * GW + F;
            uint4 t0 = __ldg((const uint4*)p0 + lane);
            float2 q;
            q = __half22float2(*(__half2*)&t0.x); a[0] += q.x; a[1] += q.y;
            q = __half22float2(*(__half2*)&t0.y); a[2] += q.x; a[3] += q.y;
            q = __half22float2(*(__half2*)&t0.z); a[4] += q.x; a[5] += q.y;
            q = __half22float2(*(__half2*)&t0.w); a[6] += q.x; a[7] += q.y;
        }
    } else {
        for (; i + 2 <= e; i += 2) {
            const __half* p0 = G + (size_t)g_csr[i]     * GW + F;
            const __half* p1 = G + (size_t)g_csr[i + 1] * GW + F;
            uint2 t0 = __ldg((const uint2*)p0 + lane);
            uint2 t1 = __ldg((const uint2*)p1 + lane);
            float2 q;
            q = __half22float2(*(__half2*)&t0.x); a[0] += q.x; a[1] += q.y;
            q = __half22float2(*(__half2*)&t0.y); a[2] += q.x; a[3] += q.y;
            q = __half22float2(*(__half2*)&t1.x); a[0] += q.x; a[1] += q.y;
            q = __half22float2(*(__half2*)&t1.y); a[2] += q.x; a[3] += q.y;
        }
        if (i < e) {
            const __half* p0 = G + (size_t)g_csr[i] * GW + F;
            uint2 t0 = __ldg((const uint2*)p0 + lane);
            float2 q;
            q = __half22float2(*(__half2*)&t0.x); a[0] += q.x; a[1] += q.y;
            q = __half22float2(*(__half2*)&t0.y); a[2] += q.x; a[3] += q.y;
        }
    }

    float inv = 1.0f / (float)max(e - s, 1);
    float r[CPL];
    if constexpr (F == 256) {
        uint4 hv = __ldg((const uint4*)(G + (size_t)v * GW) + lane);
        float2 q;
        q = __half22float2(*(__half2*)&hv.x); r[0] = q.x; r[1] = q.y;
        q = __half22float2(*(__half2*)&hv.y); r[2] = q.x; r[3] = q.y;
        q = __half22float2(*(__half2*)&hv.z); r[4] = q.x; r[5] = q.y;
        q = __half22float2(*(__half2*)&hv.w); r[6] = q.x; r[7] = q.y;
    } else {
        uint2 hv = __ldg((const uint2*)(G + (size_t)v * GW) + lane);
        float2 q;
        q = __half22float2(*(__half2*)&hv.x); r[0] = q.x; r[1] = q.y;
        q = __half22float2(*(__half2*)&hv.y); r[2] = q.x; r[3] = q.y;
    }
#pragma unroll
    for (int k = 0; k < CPL; k++) {
        r[k] += a[k] * inv + __ldg(&bias[lane * CPL + k]);
        if (RELU) r[k] = fmaxf(r[k], 0.f);
    }

    if (OUT_HALF) {
        __half* o = (__half*)outv + (size_t)v * F + lane * CPL;
        if constexpr (F == 256) {
            __half2 h0 = __floats2half2_rn(r[0], r[1]);
            __half2 h1 = __floats2half2_rn(r[2], r[3]);
            __half2 h2 = __floats2half2_rn(r[4], r[5]);
            __half2 h3 = __floats2half2_rn(r[6], r[7]);
            uint4 pk;
            pk.x = *(uint32_t*)&h0; pk.y = *(uint32_t*)&h1;
            pk.z = *(uint32_t*)&h2; pk.w = *(uint32_t*)&h3;
            *(uint4*)o = pk;
        } else {
            __half2 h0 = __floats2half2_rn(r[0], r[1]);
            __half2 h1 = __floats2half2_rn(r[2], r[3]);
            uint2 pk;
            pk.x = *(uint32_t*)&h0; pk.y = *(uint32_t*)&h1;
            *(uint2*)o = pk;
        }
    } else {
        float* o = (float*)outv + (size_t)v * F + lane * CPL;
#pragma unroll
        for (int k = 0; k < CPL; k += 4)
            *(float4*)(o + k) = make_float4(r[k], r[k + 1], r[k + 2], r[k + 3]);
    }
}

// ---------------- fp16 tensor-core GEMM: G = X @ W^T (no bias/relu) -------
// AF32=0: X fp16 [M,256] staged via cp.async.
// AF32=1: X fp32 [M,256], converted to fp16 during A staging (sync ld+cvt+sts).
// W [Nout,256] fp16 via cp.async. Block 128x128x64, 8 warps, 2-stage,
// dynamic smem 72 KB, K=256 -> 4 k-iterations.

#define PADK 72
#define ATILE (128 * PADK)
#define SMEM_GEMM (4 * ATILE * 2)   // 73728 B

__device__ __forceinline__ void ldm_x4(uint32_t& r0, uint32_t& r1, uint32_t& r2,
                                       uint32_t& r3, uint32_t addr) {
    asm volatile("ldmatrix.sync.aligned.m8n8.x4.shared.b16 {%0,%1,%2,%3}, [%4];"
                 : "=r"(r0), "=r"(r1), "=r"(r2), "=r"(r3) : "r"(addr));
}

__device__ __forceinline__ void mma16816(float* c, const uint32_t* a, const uint32_t* b) {
    asm volatile(
        "mma.sync.aligned.m16n8k16.row.col.f32.f16.f16.f32 "
        "{%0,%1,%2,%3}, {%4,%5,%6,%7}, {%8,%9}, {%0,%1,%2,%3};"
        : "+f"(c[0]), "+f"(c[1]), "+f"(c[2]), "+f"(c[3])
        : "r"(a[0]), "r"(a[1]), "r"(a[2]), "r"(a[3]), "r"(b[0]), "r"(b[1]));
}

__device__ __forceinline__ void cpa16(uint32_t sdst, const void* gsrc, int sz) {
    asm volatile("cp.async.ca.shared.global [%0], [%1], 16, %2;"
                 :: "r"(sdst), "l"(gsrc), "r"(sz));
}

template <int AF32>
__global__ __launch_bounds__(256) void k_gemm1(
    const void* __restrict__ Xin, const __half* __restrict__ W,
    __half* __restrict__ out, int M, int Nout)
{
    extern __shared__ __align__(16) __half smem[];
    int tid = threadIdx.x, lane = tid & 31, warp = tid >> 5;
    int wm = warp >> 1, wn = warp & 1;
    int bm = blockIdx.x * 128, bn = blockIdx.y * 128;

    uint32_t sbase = (uint32_t)__cvta_generic_to_shared(smem);
    uint32_t sA0 = sbase;
    uint32_t sA1 = sbase + ATILE * 2;
    uint32_t sB0 = sbase + 2 * ATILE * 2;
    uint32_t sB1 = sbase + 3 * ATILE * 2;

    float acc[2][8][4];
#pragma unroll
    for (int mi = 0; mi < 2; mi++)
#pragma unroll
        for (int ni = 0; ni < 8; ni++)
#pragma unroll
            for (int r = 0; r < 4; r++) acc[mi][ni][r] = 0.f;

#define ISSUE(st) do {                                                          \
    int kk_ = (st) * 64;                                                        \
    uint32_t dA_ = ((st) & 1) ? sA1 : sA0;                                      \
    uint32_t dB_ = ((st) & 1) ? sB1 : sB0;                                      \
    _Pragma("unroll")                                                           \
    for (int q_ = 0; q_ < 4; q_++) {                                            \
        int idx_ = tid + q_ * 256;                                              \
        int row_ = idx_ >> 3, ch_ = idx_ & 7;                                   \
        int grow_ = bm + row_;                                                  \
        if (AF32) {                                                             \
            const float* xp_ = (const float*)Xin                                \
                + (size_t)min(grow_, M - 1) * 256 + kk_ + ch_ * 8;              \
            float4 f0_ = __ldg((const float4*)xp_);                             \
            float4 f1_ = __ldg((const float4*)xp_ + 1);                         \
            if (grow_ >= M) {                                                   \
                f0_ = make_float4(0.f, 0.f, 0.f, 0.f);                          \
                f1_ = f0_;                                                      \
            }                                                                   \
            __half2 h0_ = __floats2half2_rn(f0_.x, f0_.y);                      \
            __half2 h1_ = __floats2half2_rn(f0_.z, f0_.w);                      \
            __half2 h2_ = __floats2half2_rn(f1_.x, f1_.y);                      \
            __half2 h3_ = __floats2half2_rn(f1_.z, f1_.w);                      \
            uint4 pk_;                                                          \
            pk_.x = *(uint32_t*)&h0_; pk_.y = *(uint32_t*)&h1_;                 \
            pk_.z = *(uint32_t*)&h2_; pk_.w = *(uint32_t*)&h3_;                 \
            *(uint4*)((char*)smem + (dA_ - sbase) + (row_ * PADK + ch_ * 8) * 2)\
                = pk_;                                                          \
        } else {                                                                \
            int sz_ = (grow_ < M) ? 16 : 0;                                     \
            cpa16(dA_ + (row_ * PADK + ch_ * 8) * 2,                            \
                  (const __half*)Xin + (size_t)min(grow_, M - 1) * 256          \
                      + kk_ + ch_ * 8, sz_);                                    \
        }                                                                       \
        cpa16(dB_ + (row_ * PADK + ch_ * 8) * 2,                                \
              W + (size_t)(bn + row_) * 256 + kk_ + ch_ * 8, 16);               \
    }                                                                           \
    asm volatile("cp.async.commit_group;");                                     \
} while (0)

    ISSUE(0);
    ISSUE(1);

    int g = lane >> 2, cq = lane & 3;
    int j = lane & 7, t = lane >> 3;

    for (int it = 0; it < 4; ++it) {
        if (it < 3) asm volatile("cp.async.wait_group 1;");
        else        asm volatile("cp.async.wait_group 0;");
        __syncthreads();
        uint32_t bA = (it & 1) ? sA1 : sA0;
        uint32_t bB = (it & 1) ? sB1 : sB0;
#pragma unroll
        for (int k16 = 0; k16 < 4; k16++) {
            int kh0 = k16 * 16;
            uint32_t a[2][4];
#pragma unroll
            for (int mi = 0; mi < 2; mi++) {
                int rowa = wm * 32 + mi * 16 + j + (t & 1) * 8;
                int cola = kh0 + (t >> 1) * 8;
                ldm_x4(a[mi][0], a[mi][1], a[mi][2], a[mi][3],
                       bA + (rowa * PADK + cola) * 2);
            }
            uint32_t b[8][2];
#pragma unroll
            for (int q = 0; q < 4; q++) {
                int rowb = wn * 64 + q * 16 + j + (t >> 1) * 8;
                int colb = kh0 + (t & 1) * 8;
                uint32_t r0, r1, r2, r3;
                ldm_x4(r0, r1, r2, r3, bB + (rowb * PADK + colb) * 2);
                b[2 * q][0] = r0; b[2 * q][1] = r1;
                b[2 * q + 1][0] = r2; b[2 * q + 1][1] = r3;
            }
#pragma unroll
            for (int mi = 0; mi < 2; mi++)
#pragma unroll
                for (int ni = 0; ni < 8; ni++)
                    mma16816(acc[mi][ni], a[mi], b[ni]);
        }
        if (it < 2) {
            __syncthreads();
            ISSUE(it + 2);
        }
    }
#undef ISSUE

#pragma unroll
    for (int mi = 0; mi < 2; mi++) {
        int r0 = bm + wm * 32 + mi * 16 + g;
        int r1 = r0 + 8;
#pragma unroll
        for (int ni = 0; ni < 8; ni++) {
            int col = bn + wn * 64 + ni * 8 + 2 * cq;
            if (r0 < M)
                *(__half2*)&out[(size_t)r0 * Nout + col] =
                    __floats2half2_rn(acc[mi][ni][0], acc[mi][ni][1]);
            if (r1 < M)
                *(__half2*)&out[(size_t)r1 * Nout + col] =
                    __floats2half2_rn(acc[mi][ni][2], acc[mi][ni][3]);
        }
    }
}

// ---------------- host ----------------
extern "C" void kernel_launch(void* const* d_in, const int* in_sizes, int n_in,
                              void* d_out, int out_size) {
    const float* x = nullptr;
    const int *src = nullptr, *dstp = nullptr;
    const float* Ws[3] = {0, 0, 0};
    const float* Wn[3] = {0, 0, 0};
    const float* bs[3] = {0, 0, 0};
    int c65536 = 0, c256 = 0, c32768 = 0, c800k = 0;
    for (int i = 0; i < n_in; i++) {
        int sz = in_sizes[i];
        void* p = d_in[i];
        if (sz == 12800000) {
            x = (const float*)p;
        } else if (sz == 800000) {
            if (c800k++ == 0) src = (const int*)p; else dstp = (const int*)p;
        } else if (sz == 65536) {
            int k = c65536++;
            if (k == 0) Ws[0] = (const float*)p;
            else if (k == 1) Wn[0] = (const float*)p;
            else if (k == 2) Ws[1] = (const float*)p;
            else Wn[1] = (const float*)p;
        } else if (sz == 32768) {
            if (c32768++ == 0) Ws[2] = (const float*)p; else Wn[2] = (const float*)p;
        } else if (sz == 256) {
            if (c256++ == 0) bs[0] = (const float*)p; else bs[1] = (const float*)p;
        } else if (sz == 128) {
            bs[2] = (const float*)p;
        }
    }

    __half *h16, *h16b, *G, *w16;
    int* degp;
    cudaGetSymbolAddress((void**)&h16,  g_h16);
    cudaGetSymbolAddress((void**)&h16b, g_h16b);
    cudaGetSymbolAddress((void**)&G,    g_G);
    cudaGetSymbolAddress((void**)&w16,  g_w16);
    cudaGetSymbolAddress((void**)&degp, g_deg);

    static cudaStream_t s2 = nullptr;
    static cudaEvent_t ev0, evW, evS;
    if (!s2) {
        cudaStreamCreateWithFlags(&s2, cudaStreamNonBlocking);
        cudaEventCreateWithFlags(&ev0, cudaEventDisableTiming);
        cudaEventCreateWithFlags(&evW, cudaEventDisableTiming);
        cudaEventCreateWithFlags(&evS, cudaEventDisableTiming);
        cudaFuncSetAttribute((const void*)k_gemm1<0>,
                             cudaFuncAttributeMaxDynamicSharedMemorySize, SMEM_GEMM);
        cudaFuncSetAttribute((const void*)k_gemm1<1>,
                             cudaFuncAttributeMaxDynamicSharedMemorySize, SMEM_GEMM);
    }

    const int n = N_NODES, e = N_EDGES;
    int aggGrid = (n * 32 + 255) / 256;
    int gx = (n + 127) / 128;   // 391
    dim3 g512(gx, 4);           // Nout=512
    dim3 g256(gx, 2);           // Nout=256

    // fork: s2 = weight cvt (signals evW) + CSR chain (signals evS);
    // stream0 = layer-0 GEMM (fp32 A, converts in-kernel) after evW.
    cudaEventRecord(ev0, 0);
    cudaStreamWaitEvent(s2, ev0, 0);

    k_cvt_w<<<320, 256, 0, s2>>>(Ws[0], Wn[0], Ws[1], Wn[1], Ws[2], Wn[2]);
    cudaEventRecord(evW, s2);

    cudaMemsetAsync(degp, 0, n * sizeof(int), s2);
    int e4 = e / 4;
    k_count4<<<(e4 + 255) / 256, 256, 0, s2>>>((const int4*)dstp, e4);
    k_scan<<<1, 1024, 0, s2>>>(n);
    k_fill4<<<(e4 + 255) / 256, 256, 0, s2>>>((const int4*)src, (const int4*)dstp, e4);
    cudaEventRecord(evS, s2);

    cudaStreamWaitEvent(0, evW, 0);
    // layer 0: G = x @ [Ws0;Wn0]^T  (x fp32, converted during staging)
    k_gemm1<1><<<g512, 256, SMEM_GEMM>>>(x, w16 + 0, G, n, 512);

    cudaStreamWaitEvent(0, evS, 0);   // aggc needs CSR

    // layer 0 combine -> h16b
    k_aggc<256, 1, 1><<<aggGrid, 256>>>(G, bs[0], h16b, n);
    // layer 1
    k_gemm1<0><<<g512, 256, SMEM_GEMM>>>(h16b, w16 + 131072, G, n, 512);
    k_aggc<256, 1, 1><<<aggGrid, 256>>>(G, bs[1], h16, n);
    // layer 2 (stacked [Ws2;Wn2] -> Nout=256; combine writes fp32, no relu)
    k_gemm1<0><<<g256, 256, SMEM_GEMM>>>(h16, w16 + 262144, G, n, 256);
    k_aggc<128, 0, 0><<<aggGrid, 256>>>(G, bs[2], d_out, n);
}